// round 1
// baseline (speedup 1.0000x reference)
#include <cuda_runtime.h>
#include <math.h>
#include <stdint.h>

// Problem constants
#define B_  64
#define T_  1024
#define C_  256
#define BR  64              // query tile rows
#define BC  64              // key tile rows
#define QS  260             // Q/K smem row stride in floats (conflict-free LDS.128 phasing)
#define SS  65              // S/P smem row stride in floats (conflict-free scalar rows)
#define NTILE (T_ / BR)     // 16

// Scratch (allocation-free rule: device globals)
__device__ float g_colsum[B_ * C_];            // per-batch column sums of x
__device__ float g_part[B_ * NTILE * C_];      // per (b, qtile) LN column partials

// ---------------------------------------------------------------------------
// Kernel 1: per-batch column sums  colsum[b][c] = sum_t x[b,t,c]
// Needed for degenerate rows (all keys padding-masked -> uniform 1/T over ALL T)
// ---------------------------------------------------------------------------
__global__ void colsum_kernel(const float* __restrict__ x) {
    const int b = blockIdx.x;
    const int c = threadIdx.x;
    const float* xp = x + (size_t)b * T_ * C_ + c;
    float s = 0.f;
#pragma unroll 8
    for (int t = 0; t < T_; t++) s += xp[(size_t)t * C_];
    g_colsum[b * C_ + c] = s;
}

// ---------------------------------------------------------------------------
// Kernel 2: flash-attention tile + fused LayerNorm + column partials
// One CTA per (q-tile, batch). 256 threads.
// ---------------------------------------------------------------------------
__global__ void __launch_bounds__(256, 1)
attn_kernel(const float* __restrict__ x, const int* __restrict__ km,
            const float* __restrict__ gamma, const float* __restrict__ beta)
{
    extern __shared__ float sm[];
    float* Qs  = sm;                   // [BR][QS]
    float* Ks  = Qs + BR * QS;         // [BC][QS]  (K tile == V tile; reused as O buffer)
    float* Ssm = Ks + BC * QS;         // [BR][SS]  scores / probabilities
    float* m_s = Ssm + BR * SS;        // [BR] running max
    float* l_s = m_s + BR;             // [BR] running denom
    float* a_s = l_s + BR;             // [BR] rescale alpha
    float* mu_s = a_s + BR;            // [BR] LN mean
    float* rs_s = mu_s + BR;           // [BR] LN rstd
    int*   km_s = (int*)(rs_s + BR);   // [BC] key mask

    const int qt  = blockIdx.x;
    const int b   = blockIdx.y;
    const int tid = threadIdx.x;
    const int q0  = qt * BR;
    const float* xb = x + (size_t)b * T_ * C_;

    // Load Q tile (coalesced: 64 threads cover one 1KB row)
#pragma unroll
    for (int it = 0; it < 16; it++) {
        int idx = tid + it * 256;
        int r = idx >> 6, cc = (idx & 63) << 2;
        *(float4*)(Qs + r * QS + cc) =
            *(const float4*)(xb + (size_t)(q0 + r) * C_ + cc);
    }
    if (tid < BR) { m_s[tid] = -INFINITY; l_s[tid] = 0.f; }

    // Thread mappings:
    //  stage A (S = Q K^T, 64x64): thread (i_, j_) owns rows {i_+16u}, cols {j_+16v}
    //  stage B (O += P K, 64x256): thread (tr, tc4) owns rows {tr+16u}, cols {tc4+64w+e}
    const int i_  = tid >> 4;
    const int j_  = tid & 15;
    const int tr  = i_;
    const int tc4 = j_ << 2;

    float Oacc[4][16];
#pragma unroll
    for (int u = 0; u < 4; u++)
#pragma unroll
        for (int w = 0; w < 16; w++) Oacc[u][w] = 0.f;

    for (int st = 0; st <= qt; st++) {
        const int s0 = st * BC;
        __syncthreads();   // prior stage B done with Ks/Ssm

        // Load K(=V) tile + key mask
#pragma unroll
        for (int it = 0; it < 16; it++) {
            int idx = tid + it * 256;
            int r = idx >> 6, cc = (idx & 63) << 2;
            *(float4*)(Ks + r * QS + cc) =
                *(const float4*)(xb + (size_t)(s0 + r) * C_ + cc);
        }
        if (tid < BC) km_s[tid] = km[b * T_ + s0 + tid];
        __syncthreads();

        // ---- Stage A: S = Q K^T ----
        float sacc[4][4];
#pragma unroll
        for (int u = 0; u < 4; u++)
#pragma unroll
            for (int v = 0; v < 4; v++) sacc[u][v] = 0.f;

#pragma unroll 2
        for (int kk = 0; kk < C_; kk += 4) {
            float4 af[4], bf[4];
#pragma unroll
            for (int u = 0; u < 4; u++)
                af[u] = *(const float4*)(Qs + (i_ + 16 * u) * QS + kk);
#pragma unroll
            for (int v = 0; v < 4; v++)
                bf[v] = *(const float4*)(Ks + (j_ + 16 * v) * QS + kk);
#pragma unroll
            for (int u = 0; u < 4; u++)
#pragma unroll
                for (int v = 0; v < 4; v++) {
                    sacc[u][v] += af[u].x * bf[v].x;
                    sacc[u][v] += af[u].y * bf[v].y;
                    sacc[u][v] += af[u].z * bf[v].z;
                    sacc[u][v] += af[u].w * bf[v].w;
                }
        }

        // Write masked, scaled scores (causal + key padding)
#pragma unroll
        for (int u = 0; u < 4; u++) {
            int qr = i_ + 16 * u;
#pragma unroll
            for (int v = 0; v < 4; v++) {
                int sr = j_ + 16 * v;
                bool valid = ((s0 + sr) <= (q0 + qr)) && (km_s[sr] != 0);
                Ssm[qr * SS + sr] = valid ? sacc[u][v] * 0.0625f : -INFINITY;
            }
        }
        __syncthreads();

        // ---- Online softmax (one thread per row) ----
        if (tid < BR) {
            float* row = Ssm + tid * SS;
            float mt = -INFINITY;
#pragma unroll 8
            for (int s = 0; s < BC; s++) mt = fmaxf(mt, row[s]);
            float mo = m_s[tid];
            float mn = fmaxf(mo, mt);
            float alpha, sum = 0.f;
            if (mn == -INFINITY) {             // no valid key so far
                alpha = 1.f;
#pragma unroll 8
                for (int s = 0; s < BC; s++) row[s] = 0.f;
            } else {
                alpha = (mo == -INFINITY) ? 0.f : __expf(mo - mn);
#pragma unroll 4
                for (int s = 0; s < BC; s++) {
                    float v = row[s];
                    float p = (v == -INFINITY) ? 0.f : __expf(v - mn);
                    row[s] = p;
                    sum += p;
                }
            }
            m_s[tid] = mn;
            l_s[tid] = l_s[tid] * alpha + sum;
            a_s[tid] = alpha;
        }
        __syncthreads();

        // ---- Stage B: O = alpha*O + P @ K ----
        float al[4];
#pragma unroll
        for (int u = 0; u < 4; u++) al[u] = a_s[tr + 16 * u];
#pragma unroll
        for (int u = 0; u < 4; u++)
#pragma unroll
            for (int w = 0; w < 16; w++) Oacc[u][w] *= al[u];

#pragma unroll 2
        for (int s = 0; s < BC; s++) {
            float p[4];
#pragma unroll
            for (int u = 0; u < 4; u++) p[u] = Ssm[(tr + 16 * u) * SS + s];
            float4 kf[4];
#pragma unroll
            for (int w = 0; w < 4; w++)
                kf[w] = *(const float4*)(Ks + s * QS + tc4 + 64 * w);
#pragma unroll
            for (int u = 0; u < 4; u++)
#pragma unroll
                for (int w = 0; w < 4; w++) {
                    Oacc[u][4 * w + 0] += p[u] * kf[w].x;
                    Oacc[u][4 * w + 1] += p[u] * kf[w].y;
                    Oacc[u][4 * w + 2] += p[u] * kf[w].z;
                    Oacc[u][4 * w + 3] += p[u] * kf[w].w;
                }
        }
    }

    // ---- Epilogue: normalize, degenerate fixup, stash O into Ks buffer ----
    __syncthreads();
#pragma unroll
    for (int u = 0; u < 4; u++) {
        int r = tr + 16 * u;
        float lv = l_s[r];
        bool degen = (lv == 0.f);              // all keys <= t padding-masked
        float inv = degen ? 0.f : (1.f / lv);
#pragma unroll
        for (int w = 0; w < 4; w++)
#pragma unroll
            for (int e = 0; e < 4; e++) {
                int c = tc4 + 64 * w + e;
                float val = degen ? g_colsum[b * C_ + c] * (1.f / 1024.f)
                                  : Oacc[u][4 * w + e] * inv;
                Ks[r * QS + c] = val;
            }
    }
    __syncthreads();

    // ---- LayerNorm stats (4 threads per row, two-pass) ----
    {
        int r = tid >> 2, part = tid & 3;
        const float* row = Ks + r * QS + part * 64;
        float s1 = 0.f;
#pragma unroll 8
        for (int c = 0; c < 64; c++) s1 += row[c];
        s1 += __shfl_xor_sync(0xffffffffu, s1, 1);
        s1 += __shfl_xor_sync(0xffffffffu, s1, 2);
        float mu = s1 * (1.f / 256.f);
        float s2 = 0.f;
#pragma unroll 8
        for (int c = 0; c < 64; c++) { float d = row[c] - mu; s2 += d * d; }
        s2 += __shfl_xor_sync(0xffffffffu, s2, 1);
        s2 += __shfl_xor_sync(0xffffffffu, s2, 2);
        float rstd = rsqrtf(s2 * (1.f / 256.f) + 1e-9f);
        if (part == 0) { mu_s[r] = mu; rs_s[r] = rstd; }
    }
    __syncthreads();

    // ---- Column partials over this q-tile's 64 rows ----
    {
        float acc = 0.f;
#pragma unroll 4
        for (int r = 0; r < BR; r++)
            acc += (Ks[r * QS + tid] - mu_s[r]) * rs_s[r];
        g_part[(b * NTILE + qt) * C_ + tid] = gamma[tid] * acc + 64.f * beta[tid];
    }
}

// ---------------------------------------------------------------------------
// Kernel 3: reduce the 16 q-tile partials -> mean over T
// ---------------------------------------------------------------------------
__global__ void finalize_kernel(float* __restrict__ out) {
    const int b = blockIdx.x;
    const int c = threadIdx.x;
    float s = 0.f;
#pragma unroll
    for (int qt = 0; qt < NTILE; qt++) s += g_part[(b * NTILE + qt) * C_ + c];
    out[b * C_ + c] = s * (1.f / 1024.f);
}

// ---------------------------------------------------------------------------
extern "C" void kernel_launch(void* const* d_in, const int* in_sizes, int n_in,
                              void* d_out, int out_size)
{
    const float* x     = (const float*)d_in[0];
    const int*   km    = (const int*)  d_in[1];   // bool mask delivered as int32
    const float* gamma = (const float*)d_in[2];
    const float* beta  = (const float*)d_in[3];
    float*       out   = (float*)d_out;

    const size_t smem_bytes =
        (size_t)(BR * QS + BC * QS + BR * SS + 5 * BR) * sizeof(float)
        + BC * sizeof(int);
    cudaFuncSetAttribute(attn_kernel,
                         cudaFuncAttributeMaxDynamicSharedMemorySize,
                         (int)smem_bytes);

    colsum_kernel<<<B_, C_>>>(x);
    dim3 grid(NTILE, B_);
    attn_kernel<<<grid, 256, smem_bytes>>>(x, km, gamma, beta);
    finalize_kernel<<<B_, C_>>>(out);
}

// round 3
// speedup vs baseline: 2.9841x; 2.9841x over previous
#include <cuda_runtime.h>
#include <math.h>
#include <stdint.h>

// Problem constants
#define B_  64
#define T_  1024
#define C_  256
#define BR  64              // query rows per CTA
#define BC  64              // key rows per tile
#define XS  260             // x-tile smem row stride (floats)
#define PS  68              // P/S smem row stride (floats)
#define NTILE (T_ / BR)     // 16

// Device scratch (allocation-free rule)
__device__ float g_xtf[B_ * T_ * C_];        // tf32-rounded copy of x
__device__ float g_cs16[B_ * 16 * C_];       // colsum partials
__device__ float g_colsum[B_ * C_];          // per-batch column sums (fp32 exact)
__device__ float g_part[B_ * NTILE * C_];    // per (b,qtile) LN column partials

// ---------------------------------------------------------------------------
static __device__ __forceinline__ uint32_t smem_u32(const void* p) {
    return (uint32_t)__cvta_generic_to_shared(p);
}
static __device__ __forceinline__ void cp16(uint32_t dst, const void* src) {
    asm volatile("cp.async.cg.shared.global [%0], [%1], 16;" :: "r"(dst), "l"(src));
}
static __device__ __forceinline__ uint32_t f2tf32(float v) {
    uint32_t u;
    asm("cvt.rna.tf32.f32 %0, %1;" : "=r"(u) : "f"(v));
    return u;
}
static __device__ __forceinline__ void mma_tf32(
    float& d0, float& d1, float& d2, float& d3,
    uint32_t a0, uint32_t a1, uint32_t a2, uint32_t a3,
    uint32_t b0, uint32_t b1)
{
    asm volatile(
        "mma.sync.aligned.m16n8k8.row.col.f32.tf32.tf32.f32 "
        "{%0,%1,%2,%3},{%4,%5,%6,%7},{%8,%9},{%0,%1,%2,%3};"
        : "+f"(d0), "+f"(d1), "+f"(d2), "+f"(d3)
        : "r"(a0), "r"(a1), "r"(a2), "r"(a3), "r"(b0), "r"(b1));
}
static __device__ __forceinline__ uint32_t ldsf(const float* p) {
    return __float_as_uint(*p);
}

// ---------------------------------------------------------------------------
// Kernel 1: round x -> tf32 copy, fused with column-sum partials (fp32 exact)
// ---------------------------------------------------------------------------
__global__ void round_colsum_kernel(const float* __restrict__ x) {
    const int b = blockIdx.x, ch = blockIdx.y, c = threadIdx.x;
    const size_t base = ((size_t)b * T_ + (size_t)ch * 64) * C_ + c;
    const float* xp = x + base;
    float* op = g_xtf + base;
    float s = 0.f;
#pragma unroll 8
    for (int t = 0; t < 64; t++) {
        float v = xp[(size_t)t * C_];
        s += v;
        op[(size_t)t * C_] = __uint_as_float(f2tf32(v));
    }
    g_cs16[(b * 16 + ch) * C_ + c] = s;
}

__global__ void colsum_reduce_kernel() {
    const int b = blockIdx.x, c = threadIdx.x;
    float s = 0.f;
#pragma unroll
    for (int i = 0; i < 16; i++) s += g_cs16[(b * 16 + i) * C_ + c];
    g_colsum[b * C_ + c] = s;
}

// ---------------------------------------------------------------------------
// Kernel 2: flash attention with tf32 mma.sync + fused LN + column partials
// One CTA per (qtile, batch). 256 threads = 8 warps.
// ---------------------------------------------------------------------------
__global__ void __launch_bounds__(256, 1)
attn_kernel(const int* __restrict__ km, const float* __restrict__ gamma,
            const float* __restrict__ beta)
{
    extern __shared__ float smf[];
    float* Qs = smf;                         // [64][XS]
    float* Xb0 = Qs + BR * XS;               // [64][XS] double-buffered K(=V) tile
    float* Xb1 = Xb0 + BC * XS;
    float* Ps  = Xb1 + BC * XS;              // [64][PS] scores / probs
    float* m_s = Ps + BR * PS;
    float* l_s = m_s + BR;
    float* a_s = l_s + BR;
    float* mu_s = a_s + BR;
    float* rs_s = mu_s + BR;

    const int qt   = 15 - blockIdx.x;        // heavy tiles first
    const int b    = blockIdx.y;
    const int tid  = threadIdx.x;
    const int lane = tid & 31;
    const int w    = tid >> 5;
    const int wm   = w >> 1;                 // 0..3
    const int wn   = w & 1;                  // 0..1
    const int jj   = lane & 3;
    const int g8   = lane >> 2;
    const int q0   = qt * BR;
    const int r0   = wm * 16 + g8;           // fragment row (q), second row r0+8
    const float* xb = g_xtf + (size_t)b * T_ * C_;

    // Prefetch Q tile + key tile 0
#pragma unroll
    for (int it = 0; it < 16; it++) {
        int idx = tid + it * 256;
        int r = idx >> 6, c = (idx & 63) << 2;
        cp16(smem_u32(Qs + r * XS + c), xb + (size_t)(q0 + r) * C_ + c);
    }
#pragma unroll
    for (int it = 0; it < 16; it++) {
        int idx = tid + it * 256;
        int r = idx >> 6, c = (idx & 63) << 2;
        cp16(smem_u32(Xb0 + r * XS + c), xb + (size_t)r * C_ + c);
    }
    asm volatile("cp.async.commit_group;");

    if (tid < BR) { m_s[tid] = -INFINITY; l_s[tid] = 0.f; }

    float Oacc[16][4];
#pragma unroll
    for (int nt = 0; nt < 16; nt++)
#pragma unroll
        for (int e = 0; e < 4; e++) Oacc[nt][e] = 0.f;

    for (int st = 0; st <= qt; st++) {
        float* Xc = (st & 1) ? Xb1 : Xb0;
        asm volatile("cp.async.wait_group 0;");
        __syncthreads();   // current tile ready; prev iter done with buffers & Ps

        if (st < qt) {     // prefetch next key tile
            float* Xn = (st & 1) ? Xb0 : Xb1;
            const float* src = xb + (size_t)(st + 1) * BC * C_;
#pragma unroll
            for (int it = 0; it < 16; it++) {
                int idx = tid + it * 256;
                int r = idx >> 6, c = (idx & 63) << 2;
                cp16(smem_u32(Xn + r * XS + c), src + (size_t)r * C_ + c);
            }
            asm volatile("cp.async.commit_group;");
        }

        const int s0 = st * BC;

        // key-padding mask for my 8 S-columns
        int kmr[4][2];
#pragma unroll
        for (int nt = 0; nt < 4; nt++)
#pragma unroll
            for (int e = 0; e < 2; e++)
                kmr[nt][e] = km[b * T_ + s0 + wn * 32 + nt * 8 + 2 * jj + e];

        // ---- Stage A: S = Q K^T (tf32 mma) ----
        float sacc[4][4];
#pragma unroll
        for (int nt = 0; nt < 4; nt++)
#pragma unroll
            for (int e = 0; e < 4; e++) sacc[nt][e] = 0.f;

#pragma unroll 4
        for (int k0 = 0; k0 < C_; k0 += 8) {
            uint32_t a0 = ldsf(Qs + r0 * XS + k0 + jj);
            uint32_t a1 = ldsf(Qs + (r0 + 8) * XS + k0 + jj);
            uint32_t a2 = ldsf(Qs + r0 * XS + k0 + 4 + jj);
            uint32_t a3 = ldsf(Qs + (r0 + 8) * XS + k0 + 4 + jj);
#pragma unroll
            for (int nt = 0; nt < 4; nt++) {
                const float* bp = Xc + (wn * 32 + nt * 8 + g8) * XS + k0;
                uint32_t b0 = ldsf(bp + jj);
                uint32_t b1 = ldsf(bp + 4 + jj);
                mma_tf32(sacc[nt][0], sacc[nt][1], sacc[nt][2], sacc[nt][3],
                         a0, a1, a2, a3, b0, b1);
            }
        }

        // Store masked, scaled scores to Ps
#pragma unroll
        for (int nt = 0; nt < 4; nt++) {
            int scb = wn * 32 + nt * 8 + 2 * jj;
            float v00 = (((s0 + scb)     <= (q0 + r0)) && kmr[nt][0]) ? sacc[nt][0] * 0.0625f : -INFINITY;
            float v01 = (((s0 + scb + 1) <= (q0 + r0)) && kmr[nt][1]) ? sacc[nt][1] * 0.0625f : -INFINITY;
            float v10 = (((s0 + scb)     <= (q0 + r0 + 8)) && kmr[nt][0]) ? sacc[nt][2] * 0.0625f : -INFINITY;
            float v11 = (((s0 + scb + 1) <= (q0 + r0 + 8)) && kmr[nt][1]) ? sacc[nt][3] * 0.0625f : -INFINITY;
            *(float2*)(Ps + r0 * PS + scb)       = make_float2(v00, v01);
            *(float2*)(Ps + (r0 + 8) * PS + scb) = make_float2(v10, v11);
        }
        __syncthreads();

        // ---- Online softmax: warp w owns rows 8w..8w+7; 4 lanes per row ----
        // BRANCHLESS: no sync shuffles under divergent control flow.
        {
            const int row = w * 8 + g8;
            float* rp = Ps + row * PS;
            float mt = -INFINITY;
#pragma unroll
            for (int i = 0; i < 16; i++) mt = fmaxf(mt, rp[jj + 4 * i]);
            mt = fmaxf(mt, __shfl_xor_sync(0xffffffffu, mt, 1));
            mt = fmaxf(mt, __shfl_xor_sync(0xffffffffu, mt, 2));
            const float mo = m_s[row];
            const float mn = fmaxf(mo, mt);
            // alpha: 0 when no prior valid key (O==0 there, so scaling by 0 is exact)
            const float alpha = (mo == -INFINITY) ? 0.f : __expf(mo - mn);
            float sum = 0.f;
#pragma unroll
            for (int i = 0; i < 16; i++) {
                float v = rp[jj + 4 * i];
                float p = (v == -INFINITY) ? 0.f : __expf(v - mn);  // mn==-INF => all v==-INF => p=0
                sum += p;
                rp[jj + 4 * i] = __uint_as_float(f2tf32(p));
            }
            sum += __shfl_xor_sync(0xffffffffu, sum, 1);
            sum += __shfl_xor_sync(0xffffffffu, sum, 2);
            if (jj == 0) {
                m_s[row] = mn;
                l_s[row] = l_s[row] * alpha + sum;
                a_s[row] = alpha;
            }
        }
        __syncthreads();

        // ---- Stage B: O = alpha*O + P @ X ----
        {
            const float al0 = a_s[r0], al1 = a_s[r0 + 8];
#pragma unroll
            for (int nt = 0; nt < 16; nt++) {
                Oacc[nt][0] *= al0; Oacc[nt][1] *= al0;
                Oacc[nt][2] *= al1; Oacc[nt][3] *= al1;
            }
#pragma unroll 2
            for (int s8 = 0; s8 < BC; s8 += 8) {
                uint32_t pa0 = ldsf(Ps + r0 * PS + s8 + jj);
                uint32_t pa1 = ldsf(Ps + (r0 + 8) * PS + s8 + jj);
                uint32_t pa2 = ldsf(Ps + r0 * PS + s8 + 4 + jj);
                uint32_t pa3 = ldsf(Ps + (r0 + 8) * PS + s8 + 4 + jj);
#pragma unroll
                for (int nt = 0; nt < 16; nt++) {
                    const int cn = wn * 128 + nt * 8 + g8;
                    uint32_t b0 = ldsf(Xc + (s8 + jj) * XS + cn);
                    uint32_t b1 = ldsf(Xc + (s8 + 4 + jj) * XS + cn);
                    mma_tf32(Oacc[nt][0], Oacc[nt][1], Oacc[nt][2], Oacc[nt][3],
                             pa0, pa1, pa2, pa3, b0, b1);
                }
            }
        }
    }

    // ---- Epilogue: normalize / degenerate fixup, stash O in Xb0 ----
    __syncthreads();
    float* Os = Xb0;
    {
        const float lv0 = l_s[r0], lv1 = l_s[r0 + 8];
        const bool d0 = (lv0 == 0.f), d1 = (lv1 == 0.f);
        const float inv0 = d0 ? 0.f : (1.f / lv0);
        const float inv1 = d1 ? 0.f : (1.f / lv1);
#pragma unroll
        for (int nt = 0; nt < 16; nt++)
#pragma unroll
            for (int e = 0; e < 2; e++) {
                const int c = wn * 128 + nt * 8 + 2 * jj + e;
                const float cm = g_colsum[b * C_ + c] * (1.f / 1024.f);
                Os[r0 * XS + c]       = d0 ? cm : Oacc[nt][e] * inv0;
                Os[(r0 + 8) * XS + c] = d1 ? cm : Oacc[nt][2 + e] * inv1;
            }
    }
    __syncthreads();

    // ---- LayerNorm stats (4 threads per row, two-pass) ----
    {
        const int r = tid >> 2, part = tid & 3;
        const float* row = Os + r * XS + part * 64;
        float s1 = 0.f;
#pragma unroll 8
        for (int c = 0; c < 64; c++) s1 += row[c];
        s1 += __shfl_xor_sync(0xffffffffu, s1, 1);
        s1 += __shfl_xor_sync(0xffffffffu, s1, 2);
        const float mu = s1 * (1.f / 256.f);
        float s2 = 0.f;
#pragma unroll 8
        for (int c = 0; c < 64; c++) { float d = row[c] - mu; s2 += d * d; }
        s2 += __shfl_xor_sync(0xffffffffu, s2, 1);
        s2 += __shfl_xor_sync(0xffffffffu, s2, 2);
        const float rstd = rsqrtf(s2 * (1.f / 256.f) + 1e-9f);
        if (part == 0) { mu_s[r] = mu; rs_s[r] = rstd; }
    }
    __syncthreads();

    // ---- Column partials over this q-tile's 64 rows ----
    {
        float acc = 0.f;
#pragma unroll 4
        for (int r = 0; r < BR; r++)
            acc += (Os[r * XS + tid] - mu_s[r]) * rs_s[r];
        g_part[(b * NTILE + qt) * C_ + tid] = gamma[tid] * acc + 64.f * beta[tid];
    }
}

// ---------------------------------------------------------------------------
// Kernel 3: reduce q-tile partials -> mean over T
// ---------------------------------------------------------------------------
__global__ void finalize_kernel(float* __restrict__ out) {
    const int b = blockIdx.x, c = threadIdx.x;
    float s = 0.f;
#pragma unroll
    for (int qt = 0; qt < NTILE; qt++) s += g_part[(b * NTILE + qt) * C_ + c];
    out[b * C_ + c] = s * (1.f / 1024.f);
}

// ---------------------------------------------------------------------------
extern "C" void kernel_launch(void* const* d_in, const int* in_sizes, int n_in,
                              void* d_out, int out_size)
{
    const float* x     = (const float*)d_in[0];
    const int*   km    = (const int*)  d_in[1];
    const float* gamma = (const float*)d_in[2];
    const float* beta  = (const float*)d_in[3];
    float*       out   = (float*)d_out;

    const size_t smem_bytes =
        (size_t)(BR * XS + 2 * BC * XS + BR * PS + 5 * BR) * sizeof(float);
    cudaFuncSetAttribute(attn_kernel,
                         cudaFuncAttributeMaxDynamicSharedMemorySize,
                         (int)smem_bytes);

    round_colsum_kernel<<<dim3(B_, 16), 256>>>(x);
    colsum_reduce_kernel<<<B_, 256>>>();
    attn_kernel<<<dim3(NTILE, B_), 256, smem_bytes>>>(km, gamma, beta);
    finalize_kernel<<<B_, 256>>>(out);
}

// round 4
// speedup vs baseline: 2.9854x; 1.0004x over previous
#include <cuda_runtime.h>
#include <math.h>
#include <stdint.h>

// Problem constants
#define B_  64
#define T_  1024
#define C_  256
#define BR  64              // query rows per CTA
#define BC  64              // key rows per tile
#define XS  260             // x-tile smem row stride (floats)
#define PS  68              // P/S smem row stride (floats)
#define NTILE (T_ / BR)     // 16

// Device scratch (allocation-free rule)
__device__ float g_xtf[B_ * T_ * C_];        // tf32-rounded copy of x
__device__ float g_cs16[B_ * 16 * C_];       // colsum partials
__device__ float g_colsum[B_ * C_];          // per-batch column sums (fp32 exact)
__device__ float g_part[B_ * NTILE * C_];    // per (b,qtile) LN column partials

// ---------------------------------------------------------------------------
static __device__ __forceinline__ uint32_t smem_u32(const void* p) {
    return (uint32_t)__cvta_generic_to_shared(p);
}
static __device__ __forceinline__ void cp16(uint32_t dst, const void* src) {
    asm volatile("cp.async.cg.shared.global [%0], [%1], 16;" :: "r"(dst), "l"(src));
}
static __device__ __forceinline__ uint32_t f2tf32(float v) {
    uint32_t u;
    asm("cvt.rna.tf32.f32 %0, %1;" : "=r"(u) : "f"(v));
    return u;
}
static __device__ __forceinline__ void mma_tf32(
    float& d0, float& d1, float& d2, float& d3,
    uint32_t a0, uint32_t a1, uint32_t a2, uint32_t a3,
    uint32_t b0, uint32_t b1)
{
    asm volatile(
        "mma.sync.aligned.m16n8k8.row.col.f32.tf32.tf32.f32 "
        "{%0,%1,%2,%3},{%4,%5,%6,%7},{%8,%9},{%0,%1,%2,%3};"
        : "+f"(d0), "+f"(d1), "+f"(d2), "+f"(d3)
        : "r"(a0), "r"(a1), "r"(a2), "r"(a3), "r"(b0), "r"(b1));
}
static __device__ __forceinline__ uint32_t ldsf(const float* p) {
    return __float_as_uint(*p);
}

// ---------------------------------------------------------------------------
// Kernel 1: round x -> tf32 copy, fused with column-sum partials (fp32 exact)
// ---------------------------------------------------------------------------
__global__ void round_colsum_kernel(const float* __restrict__ x) {
    const int b = blockIdx.x, ch = blockIdx.y, c = threadIdx.x;
    const size_t base = ((size_t)b * T_ + (size_t)ch * 64) * C_ + c;
    const float* xp = x + base;
    float* op = g_xtf + base;
    float s = 0.f;
#pragma unroll 8
    for (int t = 0; t < 64; t++) {
        float v = xp[(size_t)t * C_];
        s += v;
        op[(size_t)t * C_] = __uint_as_float(f2tf32(v));
    }
    g_cs16[(b * 16 + ch) * C_ + c] = s;
}

__global__ void colsum_reduce_kernel() {
    const int b = blockIdx.x, c = threadIdx.x;
    float s = 0.f;
#pragma unroll
    for (int i = 0; i < 16; i++) s += g_cs16[(b * 16 + i) * C_ + c];
    g_colsum[b * C_ + c] = s;
}

// ---------------------------------------------------------------------------
// Kernel 2: flash attention with tf32 mma.sync + fused LN + column partials
// One CTA per (qtile, batch). 256 threads = 8 warps.
// ---------------------------------------------------------------------------
__global__ void __launch_bounds__(256, 1)
attn_kernel(const int* __restrict__ km, const float* __restrict__ gamma,
            const float* __restrict__ beta)
{
    extern __shared__ float smf[];
    float* Qs = smf;                         // [64][XS]
    float* Xb0 = Qs + BR * XS;               // [64][XS] double-buffered K(=V) tile
    float* Xb1 = Xb0 + BC * XS;
    float* Ps  = Xb1 + BC * XS;              // [64][PS] scores / probs
    float* m_s = Ps + BR * PS;
    float* l_s = m_s + BR;
    float* a_s = l_s + BR;
    float* mu_s = a_s + BR;
    float* rs_s = mu_s + BR;

    const int qt   = 15 - blockIdx.x;        // heavy tiles first
    const int b    = blockIdx.y;
    const int tid  = threadIdx.x;
    const int lane = tid & 31;
    const int w    = tid >> 5;
    const int wm   = w >> 1;                 // 0..3
    const int wn   = w & 1;                  // 0..1
    const int jj   = lane & 3;
    const int g8   = lane >> 2;
    const int q0   = qt * BR;
    const int r0   = wm * 16 + g8;           // fragment row (q), second row r0+8
    const float* xb = g_xtf + (size_t)b * T_ * C_;

    // Prefetch Q tile + key tile 0
#pragma unroll
    for (int it = 0; it < 16; it++) {
        int idx = tid + it * 256;
        int r = idx >> 6, c = (idx & 63) << 2;
        cp16(smem_u32(Qs + r * XS + c), xb + (size_t)(q0 + r) * C_ + c);
    }
#pragma unroll
    for (int it = 0; it < 16; it++) {
        int idx = tid + it * 256;
        int r = idx >> 6, c = (idx & 63) << 2;
        cp16(smem_u32(Xb0 + r * XS + c), xb + (size_t)r * C_ + c);
    }
    asm volatile("cp.async.commit_group;");

    if (tid < BR) { m_s[tid] = -INFINITY; l_s[tid] = 0.f; }

    float Oacc[16][4];
#pragma unroll
    for (int nt = 0; nt < 16; nt++)
#pragma unroll
        for (int e = 0; e < 4; e++) Oacc[nt][e] = 0.f;

    for (int st = 0; st <= qt; st++) {
        float* Xc = (st & 1) ? Xb1 : Xb0;
        asm volatile("cp.async.wait_group 0;");
        __syncthreads();   // current tile ready; prev iter done with buffers & Ps

        if (st < qt) {     // prefetch next key tile
            float* Xn = (st & 1) ? Xb0 : Xb1;
            const float* src = xb + (size_t)(st + 1) * BC * C_;
#pragma unroll
            for (int it = 0; it < 16; it++) {
                int idx = tid + it * 256;
                int r = idx >> 6, c = (idx & 63) << 2;
                cp16(smem_u32(Xn + r * XS + c), src + (size_t)r * C_ + c);
            }
            asm volatile("cp.async.commit_group;");
        }

        const int s0 = st * BC;

        // key-padding mask for my 8 S-columns
        int kmr[4][2];
#pragma unroll
        for (int nt = 0; nt < 4; nt++)
#pragma unroll
            for (int e = 0; e < 2; e++)
                kmr[nt][e] = km[b * T_ + s0 + wn * 32 + nt * 8 + 2 * jj + e];

        // ---- Stage A: S = Q K^T (tf32 mma) ----
        float sacc[4][4];
#pragma unroll
        for (int nt = 0; nt < 4; nt++)
#pragma unroll
            for (int e = 0; e < 4; e++) sacc[nt][e] = 0.f;

#pragma unroll 4
        for (int k0 = 0; k0 < C_; k0 += 8) {
            uint32_t a0 = ldsf(Qs + r0 * XS + k0 + jj);
            uint32_t a1 = ldsf(Qs + (r0 + 8) * XS + k0 + jj);
            uint32_t a2 = ldsf(Qs + r0 * XS + k0 + 4 + jj);
            uint32_t a3 = ldsf(Qs + (r0 + 8) * XS + k0 + 4 + jj);
#pragma unroll
            for (int nt = 0; nt < 4; nt++) {
                const float* bp = Xc + (wn * 32 + nt * 8 + g8) * XS + k0;
                uint32_t b0 = ldsf(bp + jj);
                uint32_t b1 = ldsf(bp + 4 + jj);
                mma_tf32(sacc[nt][0], sacc[nt][1], sacc[nt][2], sacc[nt][3],
                         a0, a1, a2, a3, b0, b1);
            }
        }

        // Store masked, scaled scores to Ps
#pragma unroll
        for (int nt = 0; nt < 4; nt++) {
            int scb = wn * 32 + nt * 8 + 2 * jj;
            float v00 = (((s0 + scb)     <= (q0 + r0)) && kmr[nt][0]) ? sacc[nt][0] * 0.0625f : -INFINITY;
            float v01 = (((s0 + scb + 1) <= (q0 + r0)) && kmr[nt][1]) ? sacc[nt][1] * 0.0625f : -INFINITY;
            float v10 = (((s0 + scb)     <= (q0 + r0 + 8)) && kmr[nt][0]) ? sacc[nt][2] * 0.0625f : -INFINITY;
            float v11 = (((s0 + scb + 1) <= (q0 + r0 + 8)) && kmr[nt][1]) ? sacc[nt][3] * 0.0625f : -INFINITY;
            *(float2*)(Ps + r0 * PS + scb)       = make_float2(v00, v01);
            *(float2*)(Ps + (r0 + 8) * PS + scb) = make_float2(v10, v11);
        }
        __syncthreads();

        // ---- Online softmax: warp w owns rows 8w..8w+7; 4 lanes per row ----
        // BRANCHLESS: no sync shuffles under divergent control flow.
        {
            const int row = w * 8 + g8;
            float* rp = Ps + row * PS;
            float mt = -INFINITY;
#pragma unroll
            for (int i = 0; i < 16; i++) mt = fmaxf(mt, rp[jj + 4 * i]);
            mt = fmaxf(mt, __shfl_xor_sync(0xffffffffu, mt, 1));
            mt = fmaxf(mt, __shfl_xor_sync(0xffffffffu, mt, 2));
            const float mo = m_s[row];
            const float mn = fmaxf(mo, mt);
            // alpha: 0 when no prior valid key (O==0 there, so scaling by 0 is exact)
            const float alpha = (mo == -INFINITY) ? 0.f : __expf(mo - mn);
            float sum = 0.f;
#pragma unroll
            for (int i = 0; i < 16; i++) {
                float v = rp[jj + 4 * i];
                float p = (v == -INFINITY) ? 0.f : __expf(v - mn);  // mn==-INF => all v==-INF => p=0
                sum += p;
                rp[jj + 4 * i] = __uint_as_float(f2tf32(p));
            }
            sum += __shfl_xor_sync(0xffffffffu, sum, 1);
            sum += __shfl_xor_sync(0xffffffffu, sum, 2);
            if (jj == 0) {
                m_s[row] = mn;
                l_s[row] = l_s[row] * alpha + sum;
                a_s[row] = alpha;
            }
        }
        __syncthreads();

        // ---- Stage B: O = alpha*O + P @ X ----
        {
            const float al0 = a_s[r0], al1 = a_s[r0 + 8];
#pragma unroll
            for (int nt = 0; nt < 16; nt++) {
                Oacc[nt][0] *= al0; Oacc[nt][1] *= al0;
                Oacc[nt][2] *= al1; Oacc[nt][3] *= al1;
            }
#pragma unroll 2
            for (int s8 = 0; s8 < BC; s8 += 8) {
                uint32_t pa0 = ldsf(Ps + r0 * PS + s8 + jj);
                uint32_t pa1 = ldsf(Ps + (r0 + 8) * PS + s8 + jj);
                uint32_t pa2 = ldsf(Ps + r0 * PS + s8 + 4 + jj);
                uint32_t pa3 = ldsf(Ps + (r0 + 8) * PS + s8 + 4 + jj);
#pragma unroll
                for (int nt = 0; nt < 16; nt++) {
                    const int cn = wn * 128 + nt * 8 + g8;
                    uint32_t b0 = ldsf(Xc + (s8 + jj) * XS + cn);
                    uint32_t b1 = ldsf(Xc + (s8 + 4 + jj) * XS + cn);
                    mma_tf32(Oacc[nt][0], Oacc[nt][1], Oacc[nt][2], Oacc[nt][3],
                             pa0, pa1, pa2, pa3, b0, b1);
                }
            }
        }
    }

    // ---- Epilogue: normalize / degenerate fixup, stash O in Xb0 ----
    __syncthreads();
    float* Os = Xb0;
    {
        const float lv0 = l_s[r0], lv1 = l_s[r0 + 8];
        const bool d0 = (lv0 == 0.f), d1 = (lv1 == 0.f);
        const float inv0 = d0 ? 0.f : (1.f / lv0);
        const float inv1 = d1 ? 0.f : (1.f / lv1);
#pragma unroll
        for (int nt = 0; nt < 16; nt++)
#pragma unroll
            for (int e = 0; e < 2; e++) {
                const int c = wn * 128 + nt * 8 + 2 * jj + e;
                const float cm = g_colsum[b * C_ + c] * (1.f / 1024.f);
                Os[r0 * XS + c]       = d0 ? cm : Oacc[nt][e] * inv0;
                Os[(r0 + 8) * XS + c] = d1 ? cm : Oacc[nt][2 + e] * inv1;
            }
    }
    __syncthreads();

    // ---- LayerNorm stats (4 threads per row, two-pass) ----
    {
        const int r = tid >> 2, part = tid & 3;
        const float* row = Os + r * XS + part * 64;
        float s1 = 0.f;
#pragma unroll 8
        for (int c = 0; c < 64; c++) s1 += row[c];
        s1 += __shfl_xor_sync(0xffffffffu, s1, 1);
        s1 += __shfl_xor_sync(0xffffffffu, s1, 2);
        const float mu = s1 * (1.f / 256.f);
        float s2 = 0.f;
#pragma unroll 8
        for (int c = 0; c < 64; c++) { float d = row[c] - mu; s2 += d * d; }
        s2 += __shfl_xor_sync(0xffffffffu, s2, 1);
        s2 += __shfl_xor_sync(0xffffffffu, s2, 2);
        const float rstd = rsqrtf(s2 * (1.f / 256.f) + 1e-9f);
        if (part == 0) { mu_s[r] = mu; rs_s[r] = rstd; }
    }
    __syncthreads();

    // ---- Column partials over this q-tile's 64 rows ----
    {
        float acc = 0.f;
#pragma unroll 4
        for (int r = 0; r < BR; r++)
            acc += (Os[r * XS + tid] - mu_s[r]) * rs_s[r];
        g_part[(b * NTILE + qt) * C_ + tid] = gamma[tid] * acc + 64.f * beta[tid];
    }
}

// ---------------------------------------------------------------------------
// Kernel 3: reduce q-tile partials -> mean over T
// ---------------------------------------------------------------------------
__global__ void finalize_kernel(float* __restrict__ out) {
    const int b = blockIdx.x, c = threadIdx.x;
    float s = 0.f;
#pragma unroll
    for (int qt = 0; qt < NTILE; qt++) s += g_part[(b * NTILE + qt) * C_ + c];
    out[b * C_ + c] = s * (1.f / 1024.f);
}

// ---------------------------------------------------------------------------
extern "C" void kernel_launch(void* const* d_in, const int* in_sizes, int n_in,
                              void* d_out, int out_size)
{
    const float* x     = (const float*)d_in[0];
    const int*   km    = (const int*)  d_in[1];
    const float* gamma = (const float*)d_in[2];
    const float* beta  = (const float*)d_in[3];
    float*       out   = (float*)d_out;

    const size_t smem_bytes =
        (size_t)(BR * XS + 2 * BC * XS + BR * PS + 5 * BR) * sizeof(float);
    cudaFuncSetAttribute(attn_kernel,
                         cudaFuncAttributeMaxDynamicSharedMemorySize,
                         (int)smem_bytes);

    round_colsum_kernel<<<dim3(B_, 16), 256>>>(x);
    colsum_reduce_kernel<<<B_, 256>>>();
    attn_kernel<<<dim3(NTILE, B_), 256, smem_bytes>>>(km, gamma, beta);
    finalize_kernel<<<B_, 256>>>(out);
}